// round 7
// baseline (speedup 1.0000x reference)
#include <cuda_runtime.h>
#include <cuda_fp16.h>
#include <math.h>

#define N_NODES 50000
#define N_EDGES 800000
#define DIM     128
#define NHEAD   8

#define XPAD 132   // A-operand smem stride: 132 % 32 == 4 -> conflict-free A frags
#define WPAD 136   // B-operand smem stride: 136 % 32 == 8 -> conflict-free B frags

#define SCAN_BLOCKS ((N_NODES + 255) / 256)   // 196

// ---------------- scratch ----------------
__device__ __align__(16) __half g_hsrc[N_NODES * DIM];
__device__ __align__(16) __half g_hdst[N_NODES * DIM];
__device__ __align__(16) float  g_msg[N_NODES * DIM];
__device__ int g_cnt[N_NODES];        // histogram, then fill cursor (memset to 0)
__device__ int g_off[N_NODES + 1];    // CSR offsets by dst
__device__ int g_eid[N_EDGES];        // src node per CSR slot
// scan chain state (memset to 0 each call): [0]=ticket, [1..SCAN_BLOCKS]=flags
__device__ int g_scan_sync[1 + SCAN_BLOCKS];
__device__ int g_scan_prefix[SCAN_BLOCKS];

__device__ __forceinline__ float lrelu(float v) { return fmaxf(v, 0.2f * v); }

__device__ __forceinline__ float f2tf(float x) {
    float y;
    asm("cvt.rna.tf32.f32 %0, %1;" : "=f"(y) : "f"(x));
    return y;
}

__device__ __forceinline__ void mma_tf32(float c[4], const unsigned a[4],
                                         unsigned b0, unsigned b1) {
    asm volatile(
        "mma.sync.aligned.m16n8k8.row.col.f32.tf32.tf32.f32 "
        "{%0,%1,%2,%3},{%4,%5,%6,%7},{%8,%9},{%0,%1,%2,%3};"
        : "+f"(c[0]), "+f"(c[1]), "+f"(c[2]), "+f"(c[3])
        : "r"(a[0]), "r"(a[1]), "r"(a[2]), "r"(a[3]), "r"(b0), "r"(b1));
}

// ---------------- CSR build ----------------
__global__ void k_hist(const int* __restrict__ dst) {
    int e = blockIdx.x * blockDim.x + threadIdx.x;
    if (e < N_EDGES) atomicAdd(&g_cnt[dst[e]], 1);
}

__device__ __forceinline__ int block_incl_scan(int c, int tid) {
    __shared__ int ws[8];
    int lane = tid & 31, wid = tid >> 5;
    int v = c;
#pragma unroll
    for (int o = 1; o < 32; o <<= 1) {
        int n = __shfl_up_sync(0xFFFFFFFFu, v, o);
        if (lane >= o) v += n;
    }
    if (lane == 31) ws[wid] = v;
    __syncthreads();
    if (wid == 0) {
        int t = (lane < 8) ? ws[lane] : 0;
#pragma unroll
        for (int o = 1; o < 8; o <<= 1) {
            int n = __shfl_up_sync(0xFFFFFFFFu, t, o);
            if (lane >= o) t += n;
        }
        if (lane < 8) ws[lane] = t;
    }
    __syncthreads();
    return v + (wid > 0 ? ws[wid - 1] : 0);
}

// single-kernel chained scan: ticket ordering + flag/prefix chain
__global__ void k_scan() {
    __shared__ int s_bid, s_prev, s_total;
    int tid = threadIdx.x;
    if (tid == 0) s_bid = atomicAdd(&g_scan_sync[0], 1);
    __syncthreads();
    int bid = s_bid;

    int idx = bid * 256 + tid;
    int c = (idx < N_NODES) ? g_cnt[idx] : 0;
    int incl = block_incl_scan(c, tid);
    if (tid == 255) s_total = incl;
    __syncthreads();

    if (tid == 0) {
        int prev = 0;
        if (bid > 0) {
            while (atomicAdd(&g_scan_sync[1 + bid - 1], 0) == 0) {}
            prev = atomicAdd(&g_scan_prefix[bid - 1], 0);
        }
        g_scan_prefix[bid] = prev + s_total;
        __threadfence();
        atomicExch(&g_scan_sync[1 + bid], 1);
        s_prev = prev;
    }
    __syncthreads();

    int off = s_prev + incl - c;  // exclusive prefix
    if (idx < N_NODES) {
        g_off[idx] = off;
        g_cnt[idx] = off;  // fill cursor
    }
    if (idx == 0) g_off[N_NODES] = N_EDGES;
}

__global__ void k_fill(const int* __restrict__ src, const int* __restrict__ dst) {
    int e = blockIdx.x * blockDim.x + threadIdx.x;
    if (e < N_EDGES) {
        int pos = atomicAdd(&g_cnt[dst[e]], 1);
        g_eid[pos] = src[e];
    }
}

// ---------------- GEMM1 (tf32 HMMA): h = x @ W -> fp16, grid.y picks src/dst --------
__global__ void __launch_bounds__(256, 2)
k_gemm1(const float* __restrict__ x,
        const float* __restrict__ Wsrc, const float* __restrict__ Wdst) {
    extern __shared__ float sm[];
    float* Wsm = sm;               // [128][WPAD]
    float* xs  = sm + 128 * WPAD;  // [64][XPAD]
    const int tid = threadIdx.x;

    const float* W = blockIdx.y ? Wdst : Wsrc;
    __half* hout   = blockIdx.y ? g_hdst : g_hsrc;

    for (int i = tid; i < 128 * 32; i += 256) {
        int r = i >> 5, c4 = (i & 31) << 2;
        float4 v = ((const float4*)W)[i];
        float* p = &Wsm[r * WPAD + c4];
        p[0] = f2tf(v.x); p[1] = f2tf(v.y); p[2] = f2tf(v.z); p[3] = f2tf(v.w);
    }
    __syncthreads();

    const int warp = tid >> 5, lane = tid & 31;
    const int g = lane >> 2, t = lane & 3;
    const int m_off = (warp & 1) * 32;
    const int n_off = (warp >> 1) * 32;

    for (int r0 = blockIdx.x * 64; r0 < N_NODES; r0 += gridDim.x * 64) {
        __syncthreads();
        int rows = N_NODES - r0; if (rows > 64) rows = 64;
        for (int i = tid; i < rows * 32; i += 256) {
            int r = i >> 5, c4 = (i & 31) << 2;
            float4 v = ((const float4*)(x + (size_t)r0 * DIM))[i];
            float* p = &xs[r * XPAD + c4];
            p[0] = f2tf(v.x); p[1] = f2tf(v.y); p[2] = f2tf(v.z); p[3] = f2tf(v.w);
        }
        __syncthreads();

        float acc[2][4][4];
#pragma unroll
        for (int mt = 0; mt < 2; mt++)
#pragma unroll
            for (int j = 0; j < 4; j++)
#pragma unroll
                for (int c = 0; c < 4; c++) acc[mt][j][c] = 0.f;

#pragma unroll 4
        for (int k = 0; k < 128; k += 8) {
            unsigned a[2][4];
#pragma unroll
            for (int mt = 0; mt < 2; mt++) {
                int base = (m_off + mt * 16 + g) * XPAD + k + t;
                a[mt][0] = __float_as_uint(xs[base]);
                a[mt][1] = __float_as_uint(xs[base + 8 * XPAD]);
                a[mt][2] = __float_as_uint(xs[base + 4]);
                a[mt][3] = __float_as_uint(xs[base + 8 * XPAD + 4]);
            }
#pragma unroll
            for (int j = 0; j < 4; j++) {
                int n = n_off + 8 * j + g;
                unsigned b0 = __float_as_uint(Wsm[(k + t) * WPAD + n]);
                unsigned b1 = __float_as_uint(Wsm[(k + t + 4) * WPAD + n]);
                mma_tf32(acc[0][j], a[0], b0, b1);
                mma_tf32(acc[1][j], a[1], b0, b1);
            }
        }

#pragma unroll
        for (int mt = 0; mt < 2; mt++) {
            int rl = m_off + mt * 16 + g;
#pragma unroll
            for (int j = 0; j < 4; j++) {
                int n = n_off + 8 * j + 2 * t;
                if (rl < rows)
                    *(__half2*)&hout[(size_t)(r0 + rl) * DIM + n] =
                        __floats2half2_rn(acc[mt][j][0], acc[mt][j][1]);
                if (rl + 8 < rows)
                    *(__half2*)&hout[(size_t)(r0 + rl + 8) * DIM + n] =
                        __floats2half2_rn(acc[mt][j][2], acc[mt][j][3]);
            }
        }
    }
}

// ---------------- node-centric aggregate: one warp per dst node ----------------
__global__ void k_agg(const float* __restrict__ attn) {
    int node = (blockIdx.x * blockDim.x + threadIdx.x) >> 5;
    if (node >= N_NODES) return;
    int lane = threadIdx.x & 31;

    uint2 hdr = *(const uint2*)&g_hdst[(size_t)node * DIM + 4 * lane];
    float2 hd01 = __half22float2(*(__half2*)&hdr.x);
    float2 hd23 = __half22float2(*(__half2*)&hdr.y);
    float4 w = ((const float4*)attn)[lane];

    int beg = g_off[node], end = g_off[node + 1];
    float4 acc = make_float4(0.f, 0.f, 0.f, 0.f);
    float esum = 0.f;

    for (int base = beg; base < end; base += 32) {
        int n = end - base; if (n > 32) n = 32;
        int eid = (lane < n) ? g_eid[base + lane] : 0;

        int j = 0;
        for (; j + 2 <= n; j += 2) {
            int s0 = __shfl_sync(0xFFFFFFFFu, eid, j);
            int s1 = __shfl_sync(0xFFFFFFFFu, eid, j + 1);
            uint2 h0 = *(const uint2*)&g_hsrc[(size_t)s0 * DIM + 4 * lane];
            uint2 h1 = *(const uint2*)&g_hsrc[(size_t)s1 * DIM + 4 * lane];

            float2 a01 = __half22float2(*(__half2*)&h0.x);
            float2 a23 = __half22float2(*(__half2*)&h0.y);
            float p0 = lrelu(a01.x + hd01.x) * w.x + lrelu(a01.y + hd01.y) * w.y +
                       lrelu(a23.x + hd23.x) * w.z + lrelu(a23.y + hd23.y) * w.w;
            float2 b01 = __half22float2(*(__half2*)&h1.x);
            float2 b23 = __half22float2(*(__half2*)&h1.y);
            float p1 = lrelu(b01.x + hd01.x) * w.x + lrelu(b01.y + hd01.y) * w.y +
                       lrelu(b23.x + hd23.x) * w.z + lrelu(b23.y + hd23.y) * w.w;

            p0 += __shfl_xor_sync(0xFFFFFFFFu, p0, 1);
            p0 += __shfl_xor_sync(0xFFFFFFFFu, p0, 2);
            p1 += __shfl_xor_sync(0xFFFFFFFFu, p1, 1);
            p1 += __shfl_xor_sync(0xFFFFFFFFu, p1, 2);
            float e0 = __expf(p0), e1 = __expf(p1);

            acc.x += a01.x * e0 + b01.x * e1;
            acc.y += a01.y * e0 + b01.y * e1;
            acc.z += a23.x * e0 + b23.x * e1;
            acc.w += a23.y * e0 + b23.y * e1;
            esum += e0 + e1;
        }
        if (j < n) {
            int s0 = __shfl_sync(0xFFFFFFFFu, eid, j);
            uint2 h0 = *(const uint2*)&g_hsrc[(size_t)s0 * DIM + 4 * lane];
            float2 a01 = __half22float2(*(__half2*)&h0.x);
            float2 a23 = __half22float2(*(__half2*)&h0.y);
            float p0 = lrelu(a01.x + hd01.x) * w.x + lrelu(a01.y + hd01.y) * w.y +
                       lrelu(a23.x + hd23.x) * w.z + lrelu(a23.y + hd23.y) * w.w;
            p0 += __shfl_xor_sync(0xFFFFFFFFu, p0, 1);
            p0 += __shfl_xor_sync(0xFFFFFFFFu, p0, 2);
            float e0 = __expf(p0);
            acc.x += a01.x * e0; acc.y += a01.y * e0;
            acc.z += a23.x * e0; acc.w += a23.y * e0;
            esum += e0;
        }
    }

    float inv = 1.f / (esum + 1e-8f);
    float4 m;
    m.x = f2tf(acc.x * inv); m.y = f2tf(acc.y * inv);
    m.z = f2tf(acc.z * inv); m.w = f2tf(acc.w * inv);
    ((float4*)g_msg)[(size_t)node * 32 + lane] = m;
}

// ---------------- GEMM2 (tf32 HMMA) + bias + residual + LayerNorm ----------------
__global__ void __launch_bounds__(256, 2)
k_out(const float* __restrict__ Wout, const float* __restrict__ bias,
      const float* __restrict__ x, const float* __restrict__ gamma,
      const float* __restrict__ beta, float* __restrict__ out) {
    extern __shared__ float sm[];
    float* Wsm = sm;               // [128][WPAD]
    float* xs  = sm + 128 * WPAD;  // [64][XPAD], reused for result tile
    const int tid = threadIdx.x;

    for (int i = tid; i < 128 * 32; i += 256) {
        int r = i >> 5, c4 = (i & 31) << 2;
        float4 v = ((const float4*)Wout)[i];
        float* p = &Wsm[r * WPAD + c4];
        p[0] = f2tf(v.x); p[1] = f2tf(v.y); p[2] = f2tf(v.z); p[3] = f2tf(v.w);
    }
    __syncthreads();

    const int warp = tid >> 5, lane = tid & 31;
    const int g = lane >> 2, t = lane & 3;
    const int m_off = (warp & 1) * 32;
    const int n_off = (warp >> 1) * 32;

    for (int r0 = blockIdx.x * 64; r0 < N_NODES; r0 += gridDim.x * 64) {
        __syncthreads();
        int rows = N_NODES - r0; if (rows > 64) rows = 64;
        for (int i = tid; i < rows * 32; i += 256) {
            int r = i >> 5, c4 = (i & 31) << 2;
            float4 v = ((const float4*)(g_msg + (size_t)r0 * DIM))[i];
            *(float4*)&xs[r * XPAD + c4] = v;
        }
        __syncthreads();

        float acc[2][4][4];
#pragma unroll
        for (int mt = 0; mt < 2; mt++)
#pragma unroll
            for (int j = 0; j < 4; j++)
#pragma unroll
                for (int c = 0; c < 4; c++) acc[mt][j][c] = 0.f;

#pragma unroll 4
        for (int k = 0; k < 128; k += 8) {
            unsigned a[2][4];
#pragma unroll
            for (int mt = 0; mt < 2; mt++) {
                int base = (m_off + mt * 16 + g) * XPAD + k + t;
                a[mt][0] = __float_as_uint(xs[base]);
                a[mt][1] = __float_as_uint(xs[base + 8 * XPAD]);
                a[mt][2] = __float_as_uint(xs[base + 4]);
                a[mt][3] = __float_as_uint(xs[base + 8 * XPAD + 4]);
            }
#pragma unroll
            for (int j = 0; j < 4; j++) {
                int n = n_off + 8 * j + g;
                unsigned b0 = __float_as_uint(Wsm[(k + t) * WPAD + n]);
                unsigned b1 = __float_as_uint(Wsm[(k + t + 4) * WPAD + n]);
                mma_tf32(acc[0][j], a[0], b0, b1);
                mma_tf32(acc[1][j], a[1], b0, b1);
            }
        }
        __syncthreads();  // xs readers done; reuse xs for result tile

#pragma unroll
        for (int mt = 0; mt < 2; mt++) {
            int rl = m_off + mt * 16 + g;
#pragma unroll
            for (int j = 0; j < 4; j++) {
                int n = n_off + 8 * j + 2 * t;
                xs[rl * XPAD + n]           = acc[mt][j][0];
                xs[rl * XPAD + n + 1]       = acc[mt][j][1];
                xs[(rl + 8) * XPAD + n]     = acc[mt][j][2];
                xs[(rl + 8) * XPAD + n + 1] = acc[mt][j][3];
            }
        }
        __syncthreads();

        // LN pass: 4 threads per row, 32 cols each
        {
            int row = tid >> 2, tr = tid & 3;
            if (row < rows) {
                size_t gr = (size_t)(r0 + row);
                float vals[8][4];
                float sum = 0.f, sq = 0.f;
#pragma unroll
                for (int c = 0; c < 8; c++) {
                    int col = tr * 32 + 4 * c;
                    float4 b4 = *((const float4*)&bias[col]);
                    float4 xr = *((const float4*)&x[gr * DIM + col]);
                    float* p = &xs[row * XPAD + col];
                    float v0 = p[0] + b4.x + xr.x;
                    float v1 = p[1] + b4.y + xr.y;
                    float v2 = p[2] + b4.z + xr.z;
                    float v3 = p[3] + b4.w + xr.w;
                    vals[c][0] = v0; vals[c][1] = v1; vals[c][2] = v2; vals[c][3] = v3;
                    sum += v0 + v1 + v2 + v3;
                    sq  += v0 * v0 + v1 * v1 + v2 * v2 + v3 * v3;
                }
                sum += __shfl_xor_sync(0xFFFFFFFFu, sum, 1);
                sum += __shfl_xor_sync(0xFFFFFFFFu, sum, 2);
                sq  += __shfl_xor_sync(0xFFFFFFFFu, sq, 1);
                sq  += __shfl_xor_sync(0xFFFFFFFFu, sq, 2);
                float mean = sum * (1.f / 128.f);
                float var  = sq * (1.f / 128.f) - mean * mean;
                float rstd = rsqrtf(var + 1e-5f);
#pragma unroll
                for (int c = 0; c < 8; c++) {
                    int col = tr * 32 + 4 * c;
                    float4 g4  = *((const float4*)&gamma[col]);
                    float4 be4 = *((const float4*)&beta[col]);
                    float4 o4;
                    o4.x = (vals[c][0] - mean) * rstd * g4.x + be4.x;
                    o4.y = (vals[c][1] - mean) * rstd * g4.y + be4.y;
                    o4.z = (vals[c][2] - mean) * rstd * g4.z + be4.z;
                    o4.w = (vals[c][3] - mean) * rstd * g4.w + be4.w;
                    *((float4*)&out[gr * DIM + col]) = o4;
                }
            }
        }
    }
}

// ---------------- launch ----------------
extern "C" void kernel_launch(void* const* d_in, const int* in_sizes, int n_in,
                              void* d_out, int out_size) {
    const float* x     = (const float*)d_in[0];
    const int*   ei    = (const int*)d_in[1];
    const float* Wsrc  = (const float*)d_in[2];
    const float* Wdst  = (const float*)d_in[3];
    const float* attn  = (const float*)d_in[4];
    const float* Wout  = (const float*)d_in[5];
    const float* bias  = (const float*)d_in[6];
    const float* gamma = (const float*)d_in[7];
    const float* beta  = (const float*)d_in[8];
    float* out = (float*)d_out;
    const int* src = ei;
    const int* dst = ei + N_EDGES;

    const int SMEM = (128 * WPAD + 64 * XPAD) * 4;  // ~103 KB

    cudaFuncSetAttribute(k_gemm1, cudaFuncAttributeMaxDynamicSharedMemorySize, SMEM);
    cudaFuncSetAttribute(k_out,   cudaFuncAttributeMaxDynamicSharedMemorySize, SMEM);

    const int EBLK = (N_EDGES + 255) / 256;

    // zero CSR counters + scan chain state (memset nodes, no extra kernels)
    void* p_cnt = nullptr; void* p_sync = nullptr;
    cudaGetSymbolAddress(&p_cnt, g_cnt);
    cudaGetSymbolAddress(&p_sync, g_scan_sync);
    cudaMemsetAsync(p_cnt, 0, N_NODES * sizeof(int));
    cudaMemsetAsync(p_sync, 0, (1 + SCAN_BLOCKS) * sizeof(int));

    // CSR build
    k_hist<<<EBLK, 256>>>(dst);
    k_scan<<<SCAN_BLOCKS, 256>>>();
    k_fill<<<EBLK, 256>>>(src, dst);

    // node transforms -> fp16  (grid-stride, 2 CTAs/SM)
    k_gemm1<<<dim3(148, 2), 256, SMEM>>>(x, Wsrc, Wdst);

    // gather-aggregate (one warp per node)
    k_agg<<<(N_NODES * 32 + 255) / 256, 256>>>(attn);

    // output GEMM + residual + LN  (grid-stride, 2 CTAs/SM)
    k_out<<<296, 256, SMEM>>>(Wout, bias, x, gamma, beta, out);
}

// round 8
// speedup vs baseline: 2.2159x; 2.2159x over previous
#include <cuda_runtime.h>
#include <cuda_fp16.h>
#include <math.h>

#define N_NODES 50000
#define N_EDGES 800000
#define DIM     128
#define NHEAD   8

#define XPAD 132   // A-operand smem stride: 132 % 32 == 4 -> conflict-free A frags
#define WPAD 136   // B-operand smem stride: 136 % 32 == 8 -> conflict-free B frags

#define SCAN_BLOCKS ((N_NODES + 255) / 256)   // 196

// ---------------- scratch ----------------
__device__ __align__(16) __half g_hsrc[N_NODES * DIM];
__device__ __align__(16) __half g_hdst[N_NODES * DIM];
__device__ __align__(16) float  g_msg[N_NODES * DIM];
__device__ int g_cnt[N_NODES];        // histogram, then fill cursor (memset to 0)
__device__ int g_off[N_NODES + 1];    // CSR offsets by dst
__device__ int g_eid[N_EDGES];        // src node per CSR slot
__device__ int g_bsum[SCAN_BLOCKS];

__device__ __forceinline__ float lrelu(float v) { return fmaxf(v, 0.2f * v); }

__device__ __forceinline__ float f2tf(float x) {
    float y;
    asm("cvt.rna.tf32.f32 %0, %1;" : "=f"(y) : "f"(x));
    return y;
}

__device__ __forceinline__ void mma_tf32(float c[4], const unsigned a[4],
                                         unsigned b0, unsigned b1) {
    asm volatile(
        "mma.sync.aligned.m16n8k8.row.col.f32.tf32.tf32.f32 "
        "{%0,%1,%2,%3},{%4,%5,%6,%7},{%8,%9},{%0,%1,%2,%3};"
        : "+f"(c[0]), "+f"(c[1]), "+f"(c[2]), "+f"(c[3])
        : "r"(a[0]), "r"(a[1]), "r"(a[2]), "r"(a[3]), "r"(b0), "r"(b1));
}

// ---------------- CSR build (parallel hierarchical scan — no inter-block chains) ----
__global__ void k_hist(const int* __restrict__ dst) {
    int e = blockIdx.x * blockDim.x + threadIdx.x;
    if (e < N_EDGES) atomicAdd(&g_cnt[dst[e]], 1);
}

__device__ __forceinline__ int block_incl_scan(int c, int tid) {
    __shared__ int ws[8];
    int lane = tid & 31, wid = tid >> 5;
    int v = c;
#pragma unroll
    for (int o = 1; o < 32; o <<= 1) {
        int n = __shfl_up_sync(0xFFFFFFFFu, v, o);
        if (lane >= o) v += n;
    }
    if (lane == 31) ws[wid] = v;
    __syncthreads();
    if (wid == 0) {
        int t = (lane < 8) ? ws[lane] : 0;
#pragma unroll
        for (int o = 1; o < 8; o <<= 1) {
            int n = __shfl_up_sync(0xFFFFFFFFu, t, o);
            if (lane >= o) t += n;
        }
        if (lane < 8) ws[lane] = t;
    }
    __syncthreads();
    return v + (wid > 0 ? ws[wid - 1] : 0);
}

__global__ void k_scan1() {
    int tid = threadIdx.x;
    int idx = blockIdx.x * 256 + tid;
    int c = (idx < N_NODES) ? g_cnt[idx] : 0;
    int incl = block_incl_scan(c, tid);
    if (idx < N_NODES) g_off[idx] = incl - c;  // exclusive within block
    if (tid == 255) g_bsum[blockIdx.x] = incl;
}

__global__ void k_scan2() {
    int tid = threadIdx.x;
    int c = (tid < SCAN_BLOCKS) ? g_bsum[tid] : 0;
    int incl = block_incl_scan(c, tid);
    if (tid < SCAN_BLOCKS) g_bsum[tid] = incl - c;  // exclusive block offsets
    if (tid == 0) g_off[N_NODES] = N_EDGES;
}

__global__ void k_scan3() {
    int idx = blockIdx.x * 256 + threadIdx.x;
    if (idx < N_NODES) {
        int v = g_off[idx] + g_bsum[blockIdx.x];
        g_off[idx] = v;
        g_cnt[idx] = v;  // fill cursor
    }
}

__global__ void k_fill(const int* __restrict__ src, const int* __restrict__ dst) {
    int e = blockIdx.x * blockDim.x + threadIdx.x;
    if (e < N_EDGES) {
        int pos = atomicAdd(&g_cnt[dst[e]], 1);
        g_eid[pos] = src[e];
    }
}

// ---------------- GEMM1 (tf32 HMMA): h = x @ W -> fp16, grid.y picks src/dst --------
__global__ void __launch_bounds__(256, 2)
k_gemm1(const float* __restrict__ x,
        const float* __restrict__ Wsrc, const float* __restrict__ Wdst) {
    extern __shared__ float sm[];
    float* Wsm = sm;               // [128][WPAD]
    float* xs  = sm + 128 * WPAD;  // [64][XPAD]
    const int tid = threadIdx.x;

    const float* W = blockIdx.y ? Wdst : Wsrc;
    __half* hout   = blockIdx.y ? g_hdst : g_hsrc;

    for (int i = tid; i < 128 * 32; i += 256) {
        int r = i >> 5, c4 = (i & 31) << 2;
        float4 v = ((const float4*)W)[i];
        float* p = &Wsm[r * WPAD + c4];
        p[0] = f2tf(v.x); p[1] = f2tf(v.y); p[2] = f2tf(v.z); p[3] = f2tf(v.w);
    }
    __syncthreads();

    const int warp = tid >> 5, lane = tid & 31;
    const int g = lane >> 2, t = lane & 3;
    const int m_off = (warp & 1) * 32;
    const int n_off = (warp >> 1) * 32;

    for (int r0 = blockIdx.x * 64; r0 < N_NODES; r0 += gridDim.x * 64) {
        __syncthreads();
        int rows = N_NODES - r0; if (rows > 64) rows = 64;
        for (int i = tid; i < rows * 32; i += 256) {
            int r = i >> 5, c4 = (i & 31) << 2;
            float4 v = ((const float4*)(x + (size_t)r0 * DIM))[i];
            float* p = &xs[r * XPAD + c4];
            p[0] = f2tf(v.x); p[1] = f2tf(v.y); p[2] = f2tf(v.z); p[3] = f2tf(v.w);
        }
        __syncthreads();

        float acc[2][4][4];
#pragma unroll
        for (int mt = 0; mt < 2; mt++)
#pragma unroll
            for (int j = 0; j < 4; j++)
#pragma unroll
                for (int c = 0; c < 4; c++) acc[mt][j][c] = 0.f;

#pragma unroll 4
        for (int k = 0; k < 128; k += 8) {
            unsigned a[2][4];
#pragma unroll
            for (int mt = 0; mt < 2; mt++) {
                int base = (m_off + mt * 16 + g) * XPAD + k + t;
                a[mt][0] = __float_as_uint(xs[base]);
                a[mt][1] = __float_as_uint(xs[base + 8 * XPAD]);
                a[mt][2] = __float_as_uint(xs[base + 4]);
                a[mt][3] = __float_as_uint(xs[base + 8 * XPAD + 4]);
            }
#pragma unroll
            for (int j = 0; j < 4; j++) {
                int n = n_off + 8 * j + g;
                unsigned b0 = __float_as_uint(Wsm[(k + t) * WPAD + n]);
                unsigned b1 = __float_as_uint(Wsm[(k + t + 4) * WPAD + n]);
                mma_tf32(acc[0][j], a[0], b0, b1);
                mma_tf32(acc[1][j], a[1], b0, b1);
            }
        }

#pragma unroll
        for (int mt = 0; mt < 2; mt++) {
            int rl = m_off + mt * 16 + g;
#pragma unroll
            for (int j = 0; j < 4; j++) {
                int n = n_off + 8 * j + 2 * t;
                if (rl < rows)
                    *(__half2*)&hout[(size_t)(r0 + rl) * DIM + n] =
                        __floats2half2_rn(acc[mt][j][0], acc[mt][j][1]);
                if (rl + 8 < rows)
                    *(__half2*)&hout[(size_t)(r0 + rl + 8) * DIM + n] =
                        __floats2half2_rn(acc[mt][j][2], acc[mt][j][3]);
            }
        }
    }
}

// ---------------- node-centric aggregate: one warp per dst node ----------------
__global__ void k_agg(const float* __restrict__ attn) {
    int node = (blockIdx.x * blockDim.x + threadIdx.x) >> 5;
    if (node >= N_NODES) return;
    int lane = threadIdx.x & 31;

    uint2 hdr = *(const uint2*)&g_hdst[(size_t)node * DIM + 4 * lane];
    float2 hd01 = __half22float2(*(__half2*)&hdr.x);
    float2 hd23 = __half22float2(*(__half2*)&hdr.y);
    float4 w = ((const float4*)attn)[lane];

    int beg = g_off[node], end = g_off[node + 1];
    float4 acc = make_float4(0.f, 0.f, 0.f, 0.f);
    float esum = 0.f;

    for (int base = beg; base < end; base += 32) {
        int n = end - base; if (n > 32) n = 32;
        int eid = (lane < n) ? g_eid[base + lane] : 0;

        int j = 0;
        for (; j + 2 <= n; j += 2) {
            int s0 = __shfl_sync(0xFFFFFFFFu, eid, j);
            int s1 = __shfl_sync(0xFFFFFFFFu, eid, j + 1);
            uint2 h0 = *(const uint2*)&g_hsrc[(size_t)s0 * DIM + 4 * lane];
            uint2 h1 = *(const uint2*)&g_hsrc[(size_t)s1 * DIM + 4 * lane];

            float2 a01 = __half22float2(*(__half2*)&h0.x);
            float2 a23 = __half22float2(*(__half2*)&h0.y);
            float p0 = lrelu(a01.x + hd01.x) * w.x + lrelu(a01.y + hd01.y) * w.y +
                       lrelu(a23.x + hd23.x) * w.z + lrelu(a23.y + hd23.y) * w.w;
            float2 b01 = __half22float2(*(__half2*)&h1.x);
            float2 b23 = __half22float2(*(__half2*)&h1.y);
            float p1 = lrelu(b01.x + hd01.x) * w.x + lrelu(b01.y + hd01.y) * w.y +
                       lrelu(b23.x + hd23.x) * w.z + lrelu(b23.y + hd23.y) * w.w;

            p0 += __shfl_xor_sync(0xFFFFFFFFu, p0, 1);
            p0 += __shfl_xor_sync(0xFFFFFFFFu, p0, 2);
            p1 += __shfl_xor_sync(0xFFFFFFFFu, p1, 1);
            p1 += __shfl_xor_sync(0xFFFFFFFFu, p1, 2);
            float e0 = __expf(p0), e1 = __expf(p1);

            acc.x += a01.x * e0 + b01.x * e1;
            acc.y += a01.y * e0 + b01.y * e1;
            acc.z += a23.x * e0 + b23.x * e1;
            acc.w += a23.y * e0 + b23.y * e1;
            esum += e0 + e1;
        }
        if (j < n) {
            int s0 = __shfl_sync(0xFFFFFFFFu, eid, j);
            uint2 h0 = *(const uint2*)&g_hsrc[(size_t)s0 * DIM + 4 * lane];
            float2 a01 = __half22float2(*(__half2*)&h0.x);
            float2 a23 = __half22float2(*(__half2*)&h0.y);
            float p0 = lrelu(a01.x + hd01.x) * w.x + lrelu(a01.y + hd01.y) * w.y +
                       lrelu(a23.x + hd23.x) * w.z + lrelu(a23.y + hd23.y) * w.w;
            p0 += __shfl_xor_sync(0xFFFFFFFFu, p0, 1);
            p0 += __shfl_xor_sync(0xFFFFFFFFu, p0, 2);
            float e0 = __expf(p0);
            acc.x += a01.x * e0; acc.y += a01.y * e0;
            acc.z += a23.x * e0; acc.w += a23.y * e0;
            esum += e0;
        }
    }

    float inv = 1.f / (esum + 1e-8f);
    float4 m;
    m.x = f2tf(acc.x * inv); m.y = f2tf(acc.y * inv);
    m.z = f2tf(acc.z * inv); m.w = f2tf(acc.w * inv);
    ((float4*)g_msg)[(size_t)node * 32 + lane] = m;
}

// ---------------- GEMM2 (tf32 HMMA) + bias + residual + LayerNorm ----------------
__global__ void __launch_bounds__(256, 2)
k_out(const float* __restrict__ Wout, const float* __restrict__ bias,
      const float* __restrict__ x, const float* __restrict__ gamma,
      const float* __restrict__ beta, float* __restrict__ out) {
    extern __shared__ float sm[];
    float* Wsm = sm;               // [128][WPAD]
    float* xs  = sm + 128 * WPAD;  // [64][XPAD], reused for result tile
    const int tid = threadIdx.x;

    for (int i = tid; i < 128 * 32; i += 256) {
        int r = i >> 5, c4 = (i & 31) << 2;
        float4 v = ((const float4*)Wout)[i];
        float* p = &Wsm[r * WPAD + c4];
        p[0] = f2tf(v.x); p[1] = f2tf(v.y); p[2] = f2tf(v.z); p[3] = f2tf(v.w);
    }
    __syncthreads();

    const int warp = tid >> 5, lane = tid & 31;
    const int g = lane >> 2, t = lane & 3;
    const int m_off = (warp & 1) * 32;
    const int n_off = (warp >> 1) * 32;

    for (int r0 = blockIdx.x * 64; r0 < N_NODES; r0 += gridDim.x * 64) {
        __syncthreads();
        int rows = N_NODES - r0; if (rows > 64) rows = 64;
        for (int i = tid; i < rows * 32; i += 256) {
            int r = i >> 5, c4 = (i & 31) << 2;
            float4 v = ((const float4*)(g_msg + (size_t)r0 * DIM))[i];
            *(float4*)&xs[r * XPAD + c4] = v;
        }
        __syncthreads();

        float acc[2][4][4];
#pragma unroll
        for (int mt = 0; mt < 2; mt++)
#pragma unroll
            for (int j = 0; j < 4; j++)
#pragma unroll
                for (int c = 0; c < 4; c++) acc[mt][j][c] = 0.f;

#pragma unroll 4
        for (int k = 0; k < 128; k += 8) {
            unsigned a[2][4];
#pragma unroll
            for (int mt = 0; mt < 2; mt++) {
                int base = (m_off + mt * 16 + g) * XPAD + k + t;
                a[mt][0] = __float_as_uint(xs[base]);
                a[mt][1] = __float_as_uint(xs[base + 8 * XPAD]);
                a[mt][2] = __float_as_uint(xs[base + 4]);
                a[mt][3] = __float_as_uint(xs[base + 8 * XPAD + 4]);
            }
#pragma unroll
            for (int j = 0; j < 4; j++) {
                int n = n_off + 8 * j + g;
                unsigned b0 = __float_as_uint(Wsm[(k + t) * WPAD + n]);
                unsigned b1 = __float_as_uint(Wsm[(k + t + 4) * WPAD + n]);
                mma_tf32(acc[0][j], a[0], b0, b1);
                mma_tf32(acc[1][j], a[1], b0, b1);
            }
        }
        __syncthreads();  // xs readers done; reuse xs for result tile

#pragma unroll
        for (int mt = 0; mt < 2; mt++) {
            int rl = m_off + mt * 16 + g;
#pragma unroll
            for (int j = 0; j < 4; j++) {
                int n = n_off + 8 * j + 2 * t;
                xs[rl * XPAD + n]           = acc[mt][j][0];
                xs[rl * XPAD + n + 1]       = acc[mt][j][1];
                xs[(rl + 8) * XPAD + n]     = acc[mt][j][2];
                xs[(rl + 8) * XPAD + n + 1] = acc[mt][j][3];
            }
        }
        __syncthreads();

        // LN pass: 4 threads per row, 32 cols each
        {
            int row = tid >> 2, tr = tid & 3;
            if (row < rows) {
                size_t gr = (size_t)(r0 + row);
                float vals[8][4];
                float sum = 0.f, sq = 0.f;
#pragma unroll
                for (int c = 0; c < 8; c++) {
                    int col = tr * 32 + 4 * c;
                    float4 b4 = *((const float4*)&bias[col]);
                    float4 xr = *((const float4*)&x[gr * DIM + col]);
                    float* p = &xs[row * XPAD + col];
                    float v0 = p[0] + b4.x + xr.x;
                    float v1 = p[1] + b4.y + xr.y;
                    float v2 = p[2] + b4.z + xr.z;
                    float v3 = p[3] + b4.w + xr.w;
                    vals[c][0] = v0; vals[c][1] = v1; vals[c][2] = v2; vals[c][3] = v3;
                    sum += v0 + v1 + v2 + v3;
                    sq  += v0 * v0 + v1 * v1 + v2 * v2 + v3 * v3;
                }
                sum += __shfl_xor_sync(0xFFFFFFFFu, sum, 1);
                sum += __shfl_xor_sync(0xFFFFFFFFu, sum, 2);
                sq  += __shfl_xor_sync(0xFFFFFFFFu, sq, 1);
                sq  += __shfl_xor_sync(0xFFFFFFFFu, sq, 2);
                float mean = sum * (1.f / 128.f);
                float var  = sq * (1.f / 128.f) - mean * mean;
                float rstd = rsqrtf(var + 1e-5f);
#pragma unroll
                for (int c = 0; c < 8; c++) {
                    int col = tr * 32 + 4 * c;
                    float4 g4  = *((const float4*)&gamma[col]);
                    float4 be4 = *((const float4*)&beta[col]);
                    float4 o4;
                    o4.x = (vals[c][0] - mean) * rstd * g4.x + be4.x;
                    o4.y = (vals[c][1] - mean) * rstd * g4.y + be4.y;
                    o4.z = (vals[c][2] - mean) * rstd * g4.z + be4.z;
                    o4.w = (vals[c][3] - mean) * rstd * g4.w + be4.w;
                    *((float4*)&out[gr * DIM + col]) = o4;
                }
            }
        }
    }
}

// ---------------- launch ----------------
extern "C" void kernel_launch(void* const* d_in, const int* in_sizes, int n_in,
                              void* d_out, int out_size) {
    const float* x     = (const float*)d_in[0];
    const int*   ei    = (const int*)d_in[1];
    const float* Wsrc  = (const float*)d_in[2];
    const float* Wdst  = (const float*)d_in[3];
    const float* attn  = (const float*)d_in[4];
    const float* Wout  = (const float*)d_in[5];
    const float* bias  = (const float*)d_in[6];
    const float* gamma = (const float*)d_in[7];
    const float* beta  = (const float*)d_in[8];
    float* out = (float*)d_out;
    const int* src = ei;
    const int* dst = ei + N_EDGES;

    const int SMEM = (128 * WPAD + 64 * XPAD) * 4;  // ~103 KB

    cudaFuncSetAttribute(k_gemm1, cudaFuncAttributeMaxDynamicSharedMemorySize, SMEM);
    cudaFuncSetAttribute(k_out,   cudaFuncAttributeMaxDynamicSharedMemorySize, SMEM);

    const int EBLK = (N_EDGES + 255) / 256;

    // zero CSR counters (memset node, no extra kernel)
    void* p_cnt = nullptr;
    cudaGetSymbolAddress(&p_cnt, g_cnt);
    cudaMemsetAsync(p_cnt, 0, N_NODES * sizeof(int));

    // CSR build (hierarchical scan — fully parallel, no inter-block waits)
    k_hist <<<EBLK, 256>>>(dst);
    k_scan1<<<SCAN_BLOCKS, 256>>>();
    k_scan2<<<1, 256>>>();
    k_scan3<<<SCAN_BLOCKS, 256>>>();
    k_fill <<<EBLK, 256>>>(src, dst);

    // node transforms -> fp16  (grid-stride, 2 CTAs/SM)
    k_gemm1<<<dim3(148, 2), 256, SMEM>>>(x, Wsrc, Wdst);

    // gather-aggregate (one warp per node)
    k_agg<<<(N_NODES * 32 + 255) / 256, 256>>>(attn);

    // output GEMM + residual + LN  (grid-stride, 2 CTAs/SM)
    k_out<<<296, 256, SMEM>>>(Wout, bias, x, gamma, beta, out);
}